// round 15
// baseline (speedup 1.0000x reference)
#include <cuda_runtime.h>
#include <cuda_bf16.h>
#include <math.h>
#include <stdint.h>

// ---------------------------------------------------------------------------
// Problem constants
// ---------------------------------------------------------------------------
#define Hf 128
#define Wf 128
#define NP (Hf*Wf)          // 16384 spatial positions
#define Cin 512
#define Mch 512
#define N_PRE 6000
#define N_POST 300
#define NMS_THR 0.7f
#define MIN_SZ 16.0f
#define NW 188              // words per bitmask row (6000/32 -> 188)

// Output offsets (concatenated tuple, float32)
#define OFF_LOCS 0
#define OFF_ROIS 65536
#define OFF_RIDX 66736
#define OFF_ANCH 67036
#define OFF_CLS  132572
#define OFF_COS  247260
#define OFF_RSC  263644
#define OFF_OLD  263944

__device__ __constant__ float c_base_scales[7] =
    {16.0f, 9.0f, 14.0f, 21.0f, 33.0f, 54.0f, 93.0f};

// ---------------------------------------------------------------------------
// Device scratch (no allocations allowed)
// ---------------------------------------------------------------------------
#define XT_ROWS 34
#define XT_COLS 36
#define XT_SLAB (XT_ROWS * XT_COLS)          // 1224 floats per (tile, ch)
__device__ float g_xpad[(size_t)16 * Cin * XT_SLAB];   // ~40 MB
__device__ float g_wt[(size_t)64 * 64 * 8 * 9 * 8];    // ~9.4 MB
__device__ float g_h[(size_t)Mch * NP];     // conv output, 32 MB
__device__ float g_fg[NP];
__device__ float g_acos[NP];
__device__ float g_scale[NP];
__device__ int   g_assign[NP];
__device__ float4 g_roi4[NP];
__device__ float g_score[NP];
__device__ unsigned long long g_keys[NP];
__device__ float4 g_cand[N_PRE];
__device__ float  g_tscore[N_PRE];
__device__ unsigned int g_mask[(size_t)N_PRE * NW];    // 4.5 MB

// ---------------------------------------------------------------------------
// Packed f32x2 helpers (sm_103a): per-lane IEEE rn, bit-identical to scalar.
// ---------------------------------------------------------------------------
__device__ __forceinline__ unsigned long long f2_bcast(float x) {
    unsigned long long r;
    asm("mov.b64 %0, {%1, %1};" : "=l"(r) : "r"(__float_as_uint(x)));
    return r;
}
__device__ __forceinline__ unsigned long long f2_fma(unsigned long long a,
                                                     unsigned long long b,
                                                     unsigned long long c) {
    unsigned long long d;
    asm("fma.rn.f32x2 %0, %1, %2, %3;" : "=l"(d) : "l"(a), "l"(b), "l"(c));
    return d;
}
__device__ __forceinline__ unsigned long long f2_add(unsigned long long a,
                                                     unsigned long long b) {
    unsigned long long d;
    asm("add.rn.f32x2 %0, %1, %2;" : "=l"(d) : "l"(a), "l"(b));
    return d;
}
__device__ __forceinline__ unsigned long long f2_sub(unsigned long long a,
                                                     unsigned long long b) {
    unsigned long long d;
    asm("sub.rn.f32x2 %0, %1, %2;" : "=l"(d) : "l"(a), "l"(b));
    return d;
}
__device__ __forceinline__ void f2_unpack(float& lo, float& hi, unsigned long long v) {
    unsigned int a, b;
    asm("mov.b64 {%0, %1}, %2;" : "=r"(a), "=r"(b) : "l"(v));
    lo = __uint_as_float(a);
    hi = __uint_as_float(b);
}
__device__ __forceinline__ void kahan_add2(unsigned long long& sum,
                                           unsigned long long& comp,
                                           unsigned long long v) {
    unsigned long long y = f2_sub(v, comp);
    unsigned long long t = f2_add(sum, y);
    comp = f2_sub(f2_sub(t, sum), y);
    sum = t;
}
__device__ __forceinline__ void kahan_add(float& sum, float& comp, float v)
{
    float y = __fsub_rn(v, comp);
    float t = __fadd_rn(sum, y);
    comp = __fsub_rn(__fsub_rn(t, sum), y);
    sum = t;
}

// ---------------------------------------------------------------------------
// Kernel 0a: stage x into per-tile padded layout. Grid (c=512, tile=16),
// 256 threads, 1224 elements per block — no 64-bit div/mod.
// ---------------------------------------------------------------------------
__global__ __launch_bounds__(256)
void pad_x_kernel(const float* __restrict__ x)
{
    const int c    = blockIdx.x;
    const int tile = blockIdx.y;
    const int ty0 = (tile >> 2) * 32;
    const int tx0 = (tile & 3) * 32;
    float* dst = g_xpad + ((size_t)tile * Cin + c) * XT_SLAB;
    const float* src = x + (size_t)c * NP;
#pragma unroll
    for (int k = 0; k < 5; ++k) {
        int e = threadIdx.x + k * 256;
        if (e < XT_SLAB) {
            int ly = e / XT_COLS;
            int lx = e - ly * XT_COLS;
            int gy = ty0 - 1 + ly;
            int gx = tx0 - 1 + lx;
            float v = 0.0f;
            if (lx < 34 && gy >= 0 && gy < Hf && gx >= 0 && gx < Wf)
                v = src[gy * Wf + gx];
            dst[e] = v;
        }
    }
}

// ---------------------------------------------------------------------------
// Kernel 0b: transpose weights into [mb][ccb][c][tap][m].
// ---------------------------------------------------------------------------
#define TOTW ((size_t)64 * 64 * 576)

__global__ __launch_bounds__(256)
void pad_w_kernel(const float* __restrict__ w)
{
    unsigned int d = blockIdx.x * 256 + threadIdx.x;
    if (d >= (unsigned int)TOTW) return;
    int m   = (int)(d & 7);
    int t   = (int)((d >> 3) % 9);
    int c   = (int)((d / 72) & 7);
    int ccb = (int)((d / 576) & 63);
    int mb  = (int)(d / 36864);
    g_wt[d] = w[(size_t)(mb * 8 + m) * (Cin * 9) + (ccb * 8 + c) * 9 + t];
}

// ---------------------------------------------------------------------------
// Kernel 1: conv — R11-passing version verbatim (bit-identical math).
// ---------------------------------------------------------------------------
#define XS_C 8
#define XS_H 34
#define XS_W 36

__global__ __launch_bounds__(256, 2)
void conv3x3_kernel(const float* __restrict__ b,
                    const int*   __restrict__ mask)
{
    __shared__ float xs[XS_C * XS_H * XS_W];        // 9792 floats
    __shared__ float ws[XS_C * 9 * 8];              // 576 floats

    const int tid  = threadIdx.x;
    const int tile = blockIdx.x & 15;
    const int mb   = blockIdx.x >> 4;               // 0..63
    const int mBase = mb * 8;
    const int ty0 = ((tile >> 2) * 32);
    const int tx0 = ((tile & 3) * 32);

    const int ty = tid >> 4, tx = tid & 15;
    const int py = ty * 2, px = tx * 2;

    unsigned long long sum2[4][4], comp2[4][4];
#pragma unroll
    for (int q = 0; q < 4; ++q)
#pragma unroll
        for (int mp = 0; mp < 4; ++mp) { sum2[q][mp] = 0ull; comp2[q][mp] = 0ull; }

    const float4* xsrc0 = (const float4*)(g_xpad + (size_t)tile * Cin * XT_SLAB);
    const float4* wsrc0 = (const float4*)(g_wt + (size_t)mb * 64 * 576);

    for (int ccb = 0; ccb < 64; ++ccb) {
        __syncthreads();
        {
            const float4* src = xsrc0 + (size_t)ccb * (8 * XT_SLAB / 4);
            float4* dst = (float4*)xs;
#pragma unroll
            for (int k = 0; k < 10; ++k) {          // ceil(2448/256) = 10
                int i = tid + k * 256;
                if (i < 2448) dst[i] = src[i];
            }
        }
        {
            const float4* src = wsrc0 + (size_t)ccb * 144;
            if (tid < 144) ((float4*)ws)[tid] = src[tid];
        }
        __syncthreads();

        unsigned long long part2[4][4];
#pragma unroll
        for (int q = 0; q < 4; ++q)
#pragma unroll
            for (int mp = 0; mp < 4; ++mp) part2[q][mp] = 0ull;

#pragma unroll 1
        for (int c = 0; c < XS_C; ++c) {
            const float* xc = xs + c * (XS_H * XS_W);
            const float* wc = ws + c * 72;
#pragma unroll
            for (int ky = 0; ky < 3; ++ky) {
#pragma unroll
                for (int kx = 0; kx < 3; ++kx) {
                    const unsigned long long* wp =
                        (const unsigned long long*)(wc + (ky * 3 + kx) * 8);
                    unsigned long long wv[4];
                    wv[0] = wp[0]; wv[1] = wp[1]; wv[2] = wp[2]; wv[3] = wp[3];
                    unsigned long long xp[4];
                    xp[0] = f2_bcast(xc[(py + ky) * XS_W + (px + kx)]);
                    xp[1] = f2_bcast(xc[(py + ky) * XS_W + (px + kx + 1)]);
                    xp[2] = f2_bcast(xc[(py + ky + 1) * XS_W + (px + kx)]);
                    xp[3] = f2_bcast(xc[(py + ky + 1) * XS_W + (px + kx + 1)]);
#pragma unroll
                    for (int mp = 0; mp < 4; ++mp) {
                        part2[0][mp] = f2_fma(xp[0], wv[mp], part2[0][mp]);
                        part2[1][mp] = f2_fma(xp[1], wv[mp], part2[1][mp]);
                        part2[2][mp] = f2_fma(xp[2], wv[mp], part2[2][mp]);
                        part2[3][mp] = f2_fma(xp[3], wv[mp], part2[3][mp]);
                    }
                }
            }
        }
#pragma unroll
        for (int q = 0; q < 4; ++q)
#pragma unroll
            for (int mp = 0; mp < 4; ++mp)
                kahan_add2(sum2[q][mp], comp2[q][mp], part2[q][mp]);
    }

    float mv[4];
#pragma unroll
    for (int q = 0; q < 4; ++q) {
        int gy = ty0 + py + (q >> 1);
        int gx = tx0 + px + (q & 1);
        mv[q] = (float)mask[gy * Wf + gx];
    }
#pragma unroll
    for (int mp = 0; mp < 4; ++mp) {
        float bias0 = b[mBase + 2 * mp];
        float bias1 = b[mBase + 2 * mp + 1];
#pragma unroll
        for (int q = 0; q < 4; ++q) {
            int gy = ty0 + py + (q >> 1);
            int gx = tx0 + px + (q & 1);
            float s0, s1, c0, c1;
            f2_unpack(s0, s1, sum2[q][mp]);
            f2_unpack(c0, c1, comp2[q][mp]);
            float v0 = __fadd_rn(__fadd_rn(s0, c0), bias0);
            float v1 = __fadd_rn(__fadd_rn(s1, c1), bias1);
            v0 = fmaxf(v0, 0.0f) * mv[q];
            v1 = fmaxf(v1, 0.0f) * mv[q];
            g_h[(size_t)(mBase + 2 * mp) * NP + gy * Wf + gx] = v0;
            g_h[(size_t)(mBase + 2 * mp + 1) * NP + gy * Wf + gx] = v1;
        }
    }
}

// ---------------------------------------------------------------------------
// Kernel 2: heads — R11-passing 8-chunk loop (bit-identical per-pixel math),
// relaunched as 128 blocks x 128 threads for 2x SM coverage.
// ---------------------------------------------------------------------------
__global__ __launch_bounds__(128)
void heads_kernel(const float* __restrict__ loc_w, const float* __restrict__ loc_b,
                  const float* __restrict__ cls_w, const float* __restrict__ cls_b,
                  const float* __restrict__ cos_w, const float* __restrict__ cos_b,
                  float* __restrict__ out)
{
    __shared__ float sw[Cin * 12];
    const int tid = threadIdx.x;
    for (int i = tid; i < Cin * 12; i += 128) {
        int o = i / Cin;
        int c = i - o * Cin;
        float v;
        if (o < 4)       v = loc_w[o * Cin + c];
        else if (o < 11) v = cls_w[(o - 4) * Cin + c];
        else             v = cos_w[c];
        sw[c * 12 + o] = v;
    }
    __syncthreads();

    const int p = blockIdx.x * 128 + tid;
    float sum[12], comp[12];
#pragma unroll
    for (int o = 0; o < 12; ++o) { sum[o] = 0.0f; comp[o] = 0.0f; }

#pragma unroll 1
    for (int c = 0; c < Cin; c += 8) {
        float part[12];
#pragma unroll
        for (int o = 0; o < 12; ++o) part[o] = 0.0f;
#pragma unroll
        for (int k = 0; k < 8; ++k) {
            float hv = g_h[(size_t)(c + k) * NP + p];
            const float* wv = &sw[(c + k) * 12];
#pragma unroll
            for (int o = 0; o < 12; ++o)
                part[o] = fmaf(hv, wv[o], part[o]);
        }
#pragma unroll
        for (int o = 0; o < 12; ++o)
            kahan_add(sum[o], comp[o], part[o]);
    }
    float acc[12];
#pragma unroll
    for (int o = 0; o < 12; ++o) acc[o] = __fadd_rn(sum[o], comp[o]);

#pragma unroll
    for (int o = 0; o < 4; ++o)
        out[OFF_LOCS + p * 4 + o] = __fadd_rn(acc[o], loc_b[o]);

    float z[7];
#pragma unroll
    for (int o = 0; o < 7; ++o) {
        z[o] = __fadd_rn(acc[4 + o], cls_b[o]);
        out[OFF_CLS + p * 7 + o] = z[o];
    }
    float zmax = z[0];
    int am = 0;
#pragma unroll
    for (int o = 1; o < 7; ++o) {
        if (z[o] > zmax) zmax = z[o];
        if (z[o] > z[am]) am = o;
    }
    float ssum = 0.0f;
#pragma unroll
    for (int o = 0; o < 7; ++o) ssum = __fadd_rn(ssum, expf(__fsub_rn(z[o], zmax)));
    float p0 = __fdiv_rn(expf(__fsub_rn(z[0], zmax)), ssum);
    g_fg[p] = __fsub_rn(1.0f, p0);
    g_assign[p] = am;
    g_scale[p] = c_base_scales[am];

    float zc = __fadd_rn(acc[11], cos_b[0]);
    float s = __fdiv_rn(1.0f, __fadd_rn(1.0f, expf(-zc)));
    out[OFF_COS + p] = s;
    g_acos[p] = (s == 0.0f) ? 1e-5f : s;
}

// ---------------------------------------------------------------------------
// Kernel 3: anchors, loc2bbox, clip, validity, scores, sort keys (unchanged)
// ---------------------------------------------------------------------------
__global__ __launch_bounds__(256)
void roi_kernel(float* __restrict__ out,
                const int* __restrict__ img_h_p, const int* __restrict__ img_w_p)
{
    const int p = blockIdx.x * 256 + threadIdx.x;
    const float img_h = (float)img_h_p[0];
    const float img_w = (float)img_w_p[0];

    float a0c = g_acos[0];
    float s0  = g_scale[0];
    float anchor_h = s0 * sqrtf(1.0f / (a0c * a0c) - 1.0f);

    float ay = (float)(p >> 7) * 8.0f + 4.0f;
    float ax = (float)(p & 127) * 8.0f + 4.0f;
    float aw = g_scale[p];

    float a_0 = ay - 0.5f * anchor_h;
    float a_1 = ax - 0.5f * aw;
    float a_2 = ay + 0.5f * anchor_h;
    float a_3 = ax + 0.5f * aw;
    out[OFF_ANCH + p * 4 + 0] = a_0;
    out[OFF_ANCH + p * 4 + 1] = a_1;
    out[OFF_ANCH + p * 4 + 2] = a_2;
    out[OFF_ANCH + p * 4 + 3] = a_3;

    float h  = __fsub_rn(a_2, a_0);
    float w  = __fsub_rn(a_3, a_1);
    float cy = __fadd_rn(a_0, __fmul_rn(0.5f, h));
    float cx = __fadd_rn(a_1, __fmul_rn(0.5f, w));
    float l0 = out[OFF_LOCS + p * 4 + 0];
    float l1 = out[OFF_LOCS + p * 4 + 1];
    float l2 = out[OFF_LOCS + p * 4 + 2];
    float l3 = out[OFF_LOCS + p * 4 + 3];
    float ncy = __fadd_rn(__fmul_rn(l0, h), cy);
    float ncx = __fadd_rn(__fmul_rn(l1, w), cx);
    float nh  = __fmul_rn(expf(l2), h);
    float nw  = __fmul_rn(expf(l3), w);
    float r0 = fminf(fmaxf(__fsub_rn(ncy, __fmul_rn(0.5f, nh)), 0.0f), img_h);
    float r1 = fminf(fmaxf(__fsub_rn(ncx, __fmul_rn(0.5f, nw)), 0.0f), img_w);
    float r2 = fminf(fmaxf(__fadd_rn(ncy, __fmul_rn(0.5f, nh)), 0.0f), img_h);
    float r3 = fminf(fmaxf(__fadd_rn(ncx, __fmul_rn(0.5f, nw)), 0.0f), img_w);
    g_roi4[p] = make_float4(r0, r1, r2, r3);

    float hs = __fsub_rn(r2, r0), ws = __fsub_rn(r3, r1);
    bool valid = (g_assign[p] > 0) && (hs >= MIN_SZ) && (ws >= MIN_SZ);
    float score = valid ? g_fg[p] : -INFINITY;
    g_score[p] = score;

    unsigned int u = __float_as_uint(score);
    unsigned int m = (u & 0x80000000u) ? ~u : (u | 0x80000000u);
    g_keys[p] = ((unsigned long long)(m ^ 0xFFFFFFFFu) << 32) |
                (unsigned long long)(unsigned int)p;
}

// ---------------------------------------------------------------------------
// Kernel 4: single-block bitonic sort of 16384 keys (shfl-fused form).
// ---------------------------------------------------------------------------
__global__ __launch_bounds__(1024)
void sort_kernel(float* __restrict__ out)
{
    extern __shared__ unsigned long long sk[];
    const int tid = threadIdx.x;
    for (int i = tid; i < NP; i += 1024) sk[i] = g_keys[i];
    __syncthreads();

    for (int k = 2; k <= NP; k <<= 1) {
        for (int j = k >> 1; j >= 32; j >>= 1) {
            for (int i = tid; i < NP; i += 1024) {
                int ixj = i ^ j;
                if (ixj > i) {
                    bool up = ((i & k) == 0);
                    unsigned long long a = sk[i], b2 = sk[ixj];
                    if ((a > b2) == up) { sk[i] = b2; sk[ixj] = a; }
                }
            }
            __syncthreads();
        }
        {
            unsigned long long v[16];
#pragma unroll
            for (int s = 0; s < 16; ++s) v[s] = sk[tid + s * 1024];
            int jstart = (k >> 1) < 16 ? (k >> 1) : 16;
            for (int j = jstart; j > 0; j >>= 1) {
                bool lower = (tid & j) == 0;
#pragma unroll
                for (int s = 0; s < 16; ++s) {
                    int i = tid + s * 1024;
                    bool up = ((i & k) == 0);
                    unsigned long long a = v[s];
                    unsigned long long b2 = __shfl_xor_sync(0xFFFFFFFFu, a, j);
                    unsigned long long mn = a < b2 ? a : b2;
                    unsigned long long mx = a < b2 ? b2 : a;
                    v[s] = (lower == up) ? mn : mx;
                }
            }
#pragma unroll
            for (int s = 0; s < 16; ++s) sk[tid + s * 1024] = v[s];
            __syncthreads();
        }
    }

    for (int j = tid; j < N_PRE; j += 1024) {
        unsigned long long key = sk[j];
        int idx = (int)(key & 0xFFFFFFFFull);
        float sc = g_score[idx];
        float4 bx = make_float4(0.f, 0.f, 0.f, 0.f);
        if (sc > -INFINITY) bx = g_roi4[idx];
        g_cand[j] = bx;
        g_tscore[j] = sc;
        out[OFF_OLD + j * 4 + 0] = bx.x;
        out[OFF_OLD + j * 4 + 1] = bx.y;
        out[OFF_OLD + j * 4 + 2] = bx.z;
        out[OFF_OLD + j * 4 + 3] = bx.w;
    }
}

// ---------------------------------------------------------------------------
// Kernel 5a: NMS suppression bitmask (unchanged).
// ---------------------------------------------------------------------------
#define MASK_ROWS_PER_BLK 50
#define MASK_SM_BYTES (N_PRE * 16 + N_PRE * 4)   // boxes + areas = 120000

__global__ __launch_bounds__(256)
void nms_mask_kernel()
{
    extern __shared__ unsigned char msm[];
    float4* s_box  = (float4*)msm;
    float*  s_area = (float*)(msm + N_PRE * 16);

    const int tid = threadIdx.x;
    for (int j = tid; j < N_PRE; j += 256) {
        float4 b = g_cand[j];
        s_box[j] = b;
        s_area[j] = __fmul_rn(__fsub_rn(b.z, b.x), __fsub_rn(b.w, b.y));
    }
    __syncthreads();

    const int iBase = blockIdx.x * MASK_ROWS_PER_BLK;
    for (int item = tid; item < MASK_ROWS_PER_BLK * NW; item += 256) {
        int r = item / NW;
        int w = item - r * NW;
        int i = iBase + r;
        float4 bi = s_box[i];
        float ai = s_area[i];
        unsigned int bits = 0;
        int j0 = w * 32;
#pragma unroll 8
        for (int bidx = 0; bidx < 32; ++bidx) {
            int j = j0 + bidx;
            if (j < N_PRE) {
                float4 bj = s_box[j];
                float yy0 = fmaxf(bj.x, bi.x);
                float xx0 = fmaxf(bj.y, bi.y);
                float yy1 = fminf(bj.z, bi.z);
                float xx1 = fminf(bj.w, bi.w);
                float inter = __fmul_rn(fmaxf(__fsub_rn(yy1, yy0), 0.0f),
                                        fmaxf(__fsub_rn(xx1, xx0), 0.0f));
                float iou = __fdiv_rn(inter,
                    __fadd_rn(__fsub_rn(__fadd_rn(s_area[j], ai), inter), 1e-9f));
                if (iou > NMS_THR) bits |= (1u << bidx);
            }
        }
        g_mask[(size_t)i * NW + w] = bits;
    }
}

// ---------------------------------------------------------------------------
// Kernel 5b: serial greedy pick over the bitmask (unchanged).
// ---------------------------------------------------------------------------
__global__ __launch_bounds__(256)
void nms_pick_kernel(float* __restrict__ out)
{
    __shared__ unsigned int s_removed[NW];
    __shared__ int s_V;
    __shared__ int s_next;

    const int tid = threadIdx.x;
    if (tid == 0) s_V = N_PRE;
    __syncthreads();

    for (int j = tid; j < N_PRE; j += 256)
        if (g_tscore[j] == -INFINITY) atomicMin(&s_V, j);
    __syncthreads();
    const int V = s_V;

    for (int w = tid; w < NW; w += 256) {
        int base = w * 32;
        unsigned int init;
        if (base >= V)            init = 0xFFFFFFFFu;
        else if (base + 32 <= V)  init = 0u;
        else                      init = 0xFFFFFFFFu << (V - base);
        s_removed[w] = init;
    }
    for (int k = tid; k < N_POST; k += 256) {
        out[OFF_ROIS + k * 4 + 0] = 0.0f;
        out[OFF_ROIS + k * 4 + 1] = 0.0f;
        out[OFF_ROIS + k * 4 + 2] = 0.0f;
        out[OFF_ROIS + k * 4 + 3] = 0.0f;
        out[OFF_RIDX + k] = 0.0f;
        out[OFF_RSC + k] = 0.0f;
    }
    __syncthreads();

    int curw = 0;
    for (int k = 0; k < N_POST; ++k) {
        if (tid == 0) {
            int pick = -1;
            while (curw < NW) {
                unsigned int lw = ~s_removed[curw];
                if (lw) { pick = curw * 32 + (__ffs(lw) - 1); break; }
                ++curw;
            }
            s_next = pick;
        }
        __syncthreads();
        int i = s_next;
        if (i < 0) break;

        if (tid == 0) {
            float4 b = g_cand[i];
            out[OFF_ROIS + k * 4 + 0] = b.x;
            out[OFF_ROIS + k * 4 + 1] = b.y;
            out[OFF_ROIS + k * 4 + 2] = b.z;
            out[OFF_ROIS + k * 4 + 3] = b.w;
            out[OFF_RSC + k] = g_tscore[i];
        }
        const unsigned int* row = &g_mask[(size_t)i * NW];
        for (int w = tid; w < NW; w += 256)
            s_removed[w] |= row[w];
        __syncthreads();
    }
}

// ---------------------------------------------------------------------------
// Launch
// ---------------------------------------------------------------------------
extern "C" void kernel_launch(void* const* d_in, const int* in_sizes, int n_in,
                              void* d_out, int out_size)
{
    const float* x      = (const float*)d_in[0];
    const int*   mask   = (const int*)d_in[1];
    const float* conv_w = (const float*)d_in[2];
    const float* conv_b = (const float*)d_in[3];
    const float* loc_w  = (const float*)d_in[4];
    const float* loc_b  = (const float*)d_in[5];
    const float* cls_w  = (const float*)d_in[6];
    const float* cls_b  = (const float*)d_in[7];
    const float* cos_w  = (const float*)d_in[8];
    const float* cos_b  = (const float*)d_in[9];
    const int*   img_h  = (const int*)d_in[10];
    const int*   img_w  = (const int*)d_in[11];
    float* out = (float*)d_out;

    cudaFuncSetAttribute(sort_kernel,
        cudaFuncAttributeMaxDynamicSharedMemorySize, NP * 8);
    cudaFuncSetAttribute(nms_mask_kernel,
        cudaFuncAttributeMaxDynamicSharedMemorySize, MASK_SM_BYTES);

    {
        dim3 gx(Cin, 16);
        pad_x_kernel<<<gx, 256>>>(x);
        pad_w_kernel<<<(unsigned)((TOTW + 255) / 256), 256>>>(conv_w);
    }
    conv3x3_kernel<<<1024, 256>>>(conv_b, mask);
    heads_kernel<<<NP / 128, 128>>>(loc_w, loc_b, cls_w, cls_b, cos_w, cos_b, out);
    roi_kernel<<<NP / 256, 256>>>(out, img_h, img_w);
    sort_kernel<<<1, 1024, NP * 8>>>(out);
    nms_mask_kernel<<<N_PRE / MASK_ROWS_PER_BLK, 256, MASK_SM_BYTES>>>();
    nms_pick_kernel<<<1, 256>>>(out);
}

// round 16
// speedup vs baseline: 1.0118x; 1.0118x over previous
#include <cuda_runtime.h>
#include <cuda_bf16.h>
#include <math.h>
#include <stdint.h>

// ---------------------------------------------------------------------------
// Problem constants
// ---------------------------------------------------------------------------
#define Hf 128
#define Wf 128
#define NP (Hf*Wf)          // 16384 spatial positions
#define Cin 512
#define Mch 512
#define N_PRE 6000
#define N_POST 300
#define NMS_THR 0.7f
#define MIN_SZ 16.0f
#define NW 188              // words per bitmask row (6000/32 -> 188)

// Output offsets (concatenated tuple, float32)
#define OFF_LOCS 0
#define OFF_ROIS 65536
#define OFF_RIDX 66736
#define OFF_ANCH 67036
#define OFF_CLS  132572
#define OFF_COS  247260
#define OFF_RSC  263644
#define OFF_OLD  263944

__device__ __constant__ float c_base_scales[7] =
    {16.0f, 9.0f, 14.0f, 21.0f, 33.0f, 54.0f, 93.0f};

// ---------------------------------------------------------------------------
// Device scratch (no allocations allowed)
// ---------------------------------------------------------------------------
#define XT_ROWS 34
#define XT_COLS 36
#define XT_SLAB (XT_ROWS * XT_COLS)          // 1224 floats per (tile, ch)
__device__ float g_xpad[(size_t)16 * Cin * XT_SLAB];   // ~40 MB
__device__ float g_wt[(size_t)64 * 64 * 8 * 9 * 8];    // ~9.4 MB
__device__ float g_h[(size_t)Mch * NP];     // conv output, 32 MB
__device__ float g_fg[NP];
__device__ float g_acos[NP];
__device__ float g_scale[NP];
__device__ int   g_assign[NP];
__device__ float4 g_roi4[NP];
__device__ float g_score[NP];
__device__ unsigned long long g_keys[NP];
__device__ float4 g_cand[N_PRE];
__device__ float  g_tscore[N_PRE];
__device__ unsigned int g_mask[(size_t)N_PRE * NW];    // 4.5 MB

// ---------------------------------------------------------------------------
// Packed f32x2 helpers (sm_103a): per-lane IEEE rn, bit-identical to scalar.
// ---------------------------------------------------------------------------
__device__ __forceinline__ unsigned long long f2_bcast(float x) {
    unsigned long long r;
    asm("mov.b64 %0, {%1, %1};" : "=l"(r) : "r"(__float_as_uint(x)));
    return r;
}
__device__ __forceinline__ unsigned long long f2_fma(unsigned long long a,
                                                     unsigned long long b,
                                                     unsigned long long c) {
    unsigned long long d;
    asm("fma.rn.f32x2 %0, %1, %2, %3;" : "=l"(d) : "l"(a), "l"(b), "l"(c));
    return d;
}
__device__ __forceinline__ unsigned long long f2_add(unsigned long long a,
                                                     unsigned long long b) {
    unsigned long long d;
    asm("add.rn.f32x2 %0, %1, %2;" : "=l"(d) : "l"(a), "l"(b));
    return d;
}
__device__ __forceinline__ unsigned long long f2_sub(unsigned long long a,
                                                     unsigned long long b) {
    unsigned long long d;
    asm("sub.rn.f32x2 %0, %1, %2;" : "=l"(d) : "l"(a), "l"(b));
    return d;
}
__device__ __forceinline__ void f2_unpack(float& lo, float& hi, unsigned long long v) {
    unsigned int a, b;
    asm("mov.b64 {%0, %1}, %2;" : "=r"(a), "=r"(b) : "l"(v));
    lo = __uint_as_float(a);
    hi = __uint_as_float(b);
}
__device__ __forceinline__ void kahan_add2(unsigned long long& sum,
                                           unsigned long long& comp,
                                           unsigned long long v) {
    unsigned long long y = f2_sub(v, comp);
    unsigned long long t = f2_add(sum, y);
    comp = f2_sub(f2_sub(t, sum), y);
    sum = t;
}
__device__ __forceinline__ void kahan_add(float& sum, float& comp, float v)
{
    float y = __fsub_rn(v, comp);
    float t = __fadd_rn(sum, y);
    comp = __fsub_rn(__fsub_rn(t, sum), y);
    sum = t;
}

// ---------------------------------------------------------------------------
// Kernel 0a: stage x into per-tile padded layout. Grid (c=512, tile=16),
// 256 threads, 1224 elements per block — no 64-bit div/mod.
// ---------------------------------------------------------------------------
__global__ __launch_bounds__(256)
void pad_x_kernel(const float* __restrict__ x)
{
    const int c    = blockIdx.x;
    const int tile = blockIdx.y;
    const int ty0 = (tile >> 2) * 32;
    const int tx0 = (tile & 3) * 32;
    float* dst = g_xpad + ((size_t)tile * Cin + c) * XT_SLAB;
    const float* src = x + (size_t)c * NP;
#pragma unroll
    for (int k = 0; k < 5; ++k) {
        int e = threadIdx.x + k * 256;
        if (e < XT_SLAB) {
            int ly = e / XT_COLS;
            int lx = e - ly * XT_COLS;
            int gy = ty0 - 1 + ly;
            int gx = tx0 - 1 + lx;
            float v = 0.0f;
            if (lx < 34 && gy >= 0 && gy < Hf && gx >= 0 && gx < Wf)
                v = src[gy * Wf + gx];
            dst[e] = v;
        }
    }
}

// ---------------------------------------------------------------------------
// Kernel 0b: transpose weights into [mb][ccb][c][tap][m].
// ---------------------------------------------------------------------------
#define TOTW ((size_t)64 * 64 * 576)

__global__ __launch_bounds__(256)
void pad_w_kernel(const float* __restrict__ w)
{
    unsigned int d = blockIdx.x * 256 + threadIdx.x;
    if (d >= (unsigned int)TOTW) return;
    int m   = (int)(d & 7);
    int t   = (int)((d >> 3) % 9);
    int c   = (int)((d / 72) & 7);
    int ccb = (int)((d / 576) & 63);
    int mb  = (int)(d / 36864);
    g_wt[d] = w[(size_t)(mb * 8 + m) * (Cin * 9) + (ccb * 8 + c) * 9 + t];
}

// ---------------------------------------------------------------------------
// Kernel 1: conv — R11-passing version verbatim (bit-identical math).
// ---------------------------------------------------------------------------
#define XS_C 8
#define XS_H 34
#define XS_W 36

__global__ __launch_bounds__(256, 2)
void conv3x3_kernel(const float* __restrict__ b,
                    const int*   __restrict__ mask)
{
    __shared__ float xs[XS_C * XS_H * XS_W];        // 9792 floats
    __shared__ float ws[XS_C * 9 * 8];              // 576 floats

    const int tid  = threadIdx.x;
    const int tile = blockIdx.x & 15;
    const int mb   = blockIdx.x >> 4;               // 0..63
    const int mBase = mb * 8;
    const int ty0 = ((tile >> 2) * 32);
    const int tx0 = ((tile & 3) * 32);

    const int ty = tid >> 4, tx = tid & 15;
    const int py = ty * 2, px = tx * 2;

    unsigned long long sum2[4][4], comp2[4][4];
#pragma unroll
    for (int q = 0; q < 4; ++q)
#pragma unroll
        for (int mp = 0; mp < 4; ++mp) { sum2[q][mp] = 0ull; comp2[q][mp] = 0ull; }

    const float4* xsrc0 = (const float4*)(g_xpad + (size_t)tile * Cin * XT_SLAB);
    const float4* wsrc0 = (const float4*)(g_wt + (size_t)mb * 64 * 576);

    for (int ccb = 0; ccb < 64; ++ccb) {
        __syncthreads();
        {
            const float4* src = xsrc0 + (size_t)ccb * (8 * XT_SLAB / 4);
            float4* dst = (float4*)xs;
#pragma unroll
            for (int k = 0; k < 10; ++k) {          // ceil(2448/256) = 10
                int i = tid + k * 256;
                if (i < 2448) dst[i] = src[i];
            }
        }
        {
            const float4* src = wsrc0 + (size_t)ccb * 144;
            if (tid < 144) ((float4*)ws)[tid] = src[tid];
        }
        __syncthreads();

        unsigned long long part2[4][4];
#pragma unroll
        for (int q = 0; q < 4; ++q)
#pragma unroll
            for (int mp = 0; mp < 4; ++mp) part2[q][mp] = 0ull;

#pragma unroll 1
        for (int c = 0; c < XS_C; ++c) {
            const float* xc = xs + c * (XS_H * XS_W);
            const float* wc = ws + c * 72;
#pragma unroll
            for (int ky = 0; ky < 3; ++ky) {
#pragma unroll
                for (int kx = 0; kx < 3; ++kx) {
                    const unsigned long long* wp =
                        (const unsigned long long*)(wc + (ky * 3 + kx) * 8);
                    unsigned long long wv[4];
                    wv[0] = wp[0]; wv[1] = wp[1]; wv[2] = wp[2]; wv[3] = wp[3];
                    unsigned long long xp[4];
                    xp[0] = f2_bcast(xc[(py + ky) * XS_W + (px + kx)]);
                    xp[1] = f2_bcast(xc[(py + ky) * XS_W + (px + kx + 1)]);
                    xp[2] = f2_bcast(xc[(py + ky + 1) * XS_W + (px + kx)]);
                    xp[3] = f2_bcast(xc[(py + ky + 1) * XS_W + (px + kx + 1)]);
#pragma unroll
                    for (int mp = 0; mp < 4; ++mp) {
                        part2[0][mp] = f2_fma(xp[0], wv[mp], part2[0][mp]);
                        part2[1][mp] = f2_fma(xp[1], wv[mp], part2[1][mp]);
                        part2[2][mp] = f2_fma(xp[2], wv[mp], part2[2][mp]);
                        part2[3][mp] = f2_fma(xp[3], wv[mp], part2[3][mp]);
                    }
                }
            }
        }
#pragma unroll
        for (int q = 0; q < 4; ++q)
#pragma unroll
            for (int mp = 0; mp < 4; ++mp)
                kahan_add2(sum2[q][mp], comp2[q][mp], part2[q][mp]);
    }

    float mv[4];
#pragma unroll
    for (int q = 0; q < 4; ++q) {
        int gy = ty0 + py + (q >> 1);
        int gx = tx0 + px + (q & 1);
        mv[q] = (float)mask[gy * Wf + gx];
    }
#pragma unroll
    for (int mp = 0; mp < 4; ++mp) {
        float bias0 = b[mBase + 2 * mp];
        float bias1 = b[mBase + 2 * mp + 1];
#pragma unroll
        for (int q = 0; q < 4; ++q) {
            int gy = ty0 + py + (q >> 1);
            int gx = tx0 + px + (q & 1);
            float s0, s1, c0, c1;
            f2_unpack(s0, s1, sum2[q][mp]);
            f2_unpack(c0, c1, comp2[q][mp]);
            float v0 = __fadd_rn(__fadd_rn(s0, c0), bias0);
            float v1 = __fadd_rn(__fadd_rn(s1, c1), bias1);
            v0 = fmaxf(v0, 0.0f) * mv[q];
            v1 = fmaxf(v1, 0.0f) * mv[q];
            g_h[(size_t)(mBase + 2 * mp) * NP + gy * Wf + gx] = v0;
            g_h[(size_t)(mBase + 2 * mp + 1) * NP + gy * Wf + gx] = v1;
        }
    }
}

// ---------------------------------------------------------------------------
// Kernel 2: heads — R11-passing version verbatim (64 blocks x 256 threads,
// 8-chunk loop; best measured at 62 us).
// ---------------------------------------------------------------------------
__global__ __launch_bounds__(256)
void heads_kernel(const float* __restrict__ loc_w, const float* __restrict__ loc_b,
                  const float* __restrict__ cls_w, const float* __restrict__ cls_b,
                  const float* __restrict__ cos_w, const float* __restrict__ cos_b,
                  float* __restrict__ out)
{
    __shared__ float sw[Cin * 12];
    const int tid = threadIdx.x;
    for (int i = tid; i < Cin * 12; i += 256) {
        int o = i / Cin;
        int c = i - o * Cin;
        float v;
        if (o < 4)       v = loc_w[o * Cin + c];
        else if (o < 11) v = cls_w[(o - 4) * Cin + c];
        else             v = cos_w[c];
        sw[c * 12 + o] = v;
    }
    __syncthreads();

    const int p = blockIdx.x * 256 + tid;
    float sum[12], comp[12];
#pragma unroll
    for (int o = 0; o < 12; ++o) { sum[o] = 0.0f; comp[o] = 0.0f; }

#pragma unroll 1
    for (int c = 0; c < Cin; c += 8) {
        float part[12];
#pragma unroll
        for (int o = 0; o < 12; ++o) part[o] = 0.0f;
#pragma unroll
        for (int k = 0; k < 8; ++k) {
            float hv = g_h[(size_t)(c + k) * NP + p];
            const float* wv = &sw[(c + k) * 12];
#pragma unroll
            for (int o = 0; o < 12; ++o)
                part[o] = fmaf(hv, wv[o], part[o]);
        }
#pragma unroll
        for (int o = 0; o < 12; ++o)
            kahan_add(sum[o], comp[o], part[o]);
    }
    float acc[12];
#pragma unroll
    for (int o = 0; o < 12; ++o) acc[o] = __fadd_rn(sum[o], comp[o]);

#pragma unroll
    for (int o = 0; o < 4; ++o)
        out[OFF_LOCS + p * 4 + o] = __fadd_rn(acc[o], loc_b[o]);

    float z[7];
#pragma unroll
    for (int o = 0; o < 7; ++o) {
        z[o] = __fadd_rn(acc[4 + o], cls_b[o]);
        out[OFF_CLS + p * 7 + o] = z[o];
    }
    float zmax = z[0];
    int am = 0;
#pragma unroll
    for (int o = 1; o < 7; ++o) {
        if (z[o] > zmax) zmax = z[o];
        if (z[o] > z[am]) am = o;
    }
    float ssum = 0.0f;
#pragma unroll
    for (int o = 0; o < 7; ++o) ssum = __fadd_rn(ssum, expf(__fsub_rn(z[o], zmax)));
    float p0 = __fdiv_rn(expf(__fsub_rn(z[0], zmax)), ssum);
    g_fg[p] = __fsub_rn(1.0f, p0);
    g_assign[p] = am;
    g_scale[p] = c_base_scales[am];

    float zc = __fadd_rn(acc[11], cos_b[0]);
    float s = __fdiv_rn(1.0f, __fadd_rn(1.0f, expf(-zc)));
    out[OFF_COS + p] = s;
    g_acos[p] = (s == 0.0f) ? 1e-5f : s;
}

// ---------------------------------------------------------------------------
// Kernel 3: anchors, loc2bbox, clip, validity, scores, sort keys (unchanged)
// ---------------------------------------------------------------------------
__global__ __launch_bounds__(256)
void roi_kernel(float* __restrict__ out,
                const int* __restrict__ img_h_p, const int* __restrict__ img_w_p)
{
    const int p = blockIdx.x * 256 + threadIdx.x;
    const float img_h = (float)img_h_p[0];
    const float img_w = (float)img_w_p[0];

    float a0c = g_acos[0];
    float s0  = g_scale[0];
    float anchor_h = s0 * sqrtf(1.0f / (a0c * a0c) - 1.0f);

    float ay = (float)(p >> 7) * 8.0f + 4.0f;
    float ax = (float)(p & 127) * 8.0f + 4.0f;
    float aw = g_scale[p];

    float a_0 = ay - 0.5f * anchor_h;
    float a_1 = ax - 0.5f * aw;
    float a_2 = ay + 0.5f * anchor_h;
    float a_3 = ax + 0.5f * aw;
    out[OFF_ANCH + p * 4 + 0] = a_0;
    out[OFF_ANCH + p * 4 + 1] = a_1;
    out[OFF_ANCH + p * 4 + 2] = a_2;
    out[OFF_ANCH + p * 4 + 3] = a_3;

    float h  = __fsub_rn(a_2, a_0);
    float w  = __fsub_rn(a_3, a_1);
    float cy = __fadd_rn(a_0, __fmul_rn(0.5f, h));
    float cx = __fadd_rn(a_1, __fmul_rn(0.5f, w));
    float l0 = out[OFF_LOCS + p * 4 + 0];
    float l1 = out[OFF_LOCS + p * 4 + 1];
    float l2 = out[OFF_LOCS + p * 4 + 2];
    float l3 = out[OFF_LOCS + p * 4 + 3];
    float ncy = __fadd_rn(__fmul_rn(l0, h), cy);
    float ncx = __fadd_rn(__fmul_rn(l1, w), cx);
    float nh  = __fmul_rn(expf(l2), h);
    float nw  = __fmul_rn(expf(l3), w);
    float r0 = fminf(fmaxf(__fsub_rn(ncy, __fmul_rn(0.5f, nh)), 0.0f), img_h);
    float r1 = fminf(fmaxf(__fsub_rn(ncx, __fmul_rn(0.5f, nw)), 0.0f), img_w);
    float r2 = fminf(fmaxf(__fadd_rn(ncy, __fmul_rn(0.5f, nh)), 0.0f), img_h);
    float r3 = fminf(fmaxf(__fadd_rn(ncx, __fmul_rn(0.5f, nw)), 0.0f), img_w);
    g_roi4[p] = make_float4(r0, r1, r2, r3);

    float hs = __fsub_rn(r2, r0), ws = __fsub_rn(r3, r1);
    bool valid = (g_assign[p] > 0) && (hs >= MIN_SZ) && (ws >= MIN_SZ);
    float score = valid ? g_fg[p] : -INFINITY;
    g_score[p] = score;

    unsigned int u = __float_as_uint(score);
    unsigned int m = (u & 0x80000000u) ? ~u : (u | 0x80000000u);
    g_keys[p] = ((unsigned long long)(m ^ 0xFFFFFFFFu) << 32) |
                (unsigned long long)(unsigned int)p;
}

// ---------------------------------------------------------------------------
// Kernel 4: single-block bitonic sort of 16384 keys (shfl-fused form).
// ---------------------------------------------------------------------------
__global__ __launch_bounds__(1024)
void sort_kernel(float* __restrict__ out)
{
    extern __shared__ unsigned long long sk[];
    const int tid = threadIdx.x;
    for (int i = tid; i < NP; i += 1024) sk[i] = g_keys[i];
    __syncthreads();

    for (int k = 2; k <= NP; k <<= 1) {
        for (int j = k >> 1; j >= 32; j >>= 1) {
            for (int i = tid; i < NP; i += 1024) {
                int ixj = i ^ j;
                if (ixj > i) {
                    bool up = ((i & k) == 0);
                    unsigned long long a = sk[i], b2 = sk[ixj];
                    if ((a > b2) == up) { sk[i] = b2; sk[ixj] = a; }
                }
            }
            __syncthreads();
        }
        {
            unsigned long long v[16];
#pragma unroll
            for (int s = 0; s < 16; ++s) v[s] = sk[tid + s * 1024];
            int jstart = (k >> 1) < 16 ? (k >> 1) : 16;
            for (int j = jstart; j > 0; j >>= 1) {
                bool lower = (tid & j) == 0;
#pragma unroll
                for (int s = 0; s < 16; ++s) {
                    int i = tid + s * 1024;
                    bool up = ((i & k) == 0);
                    unsigned long long a = v[s];
                    unsigned long long b2 = __shfl_xor_sync(0xFFFFFFFFu, a, j);
                    unsigned long long mn = a < b2 ? a : b2;
                    unsigned long long mx = a < b2 ? b2 : a;
                    v[s] = (lower == up) ? mn : mx;
                }
            }
#pragma unroll
            for (int s = 0; s < 16; ++s) sk[tid + s * 1024] = v[s];
            __syncthreads();
        }
    }

    for (int j = tid; j < N_PRE; j += 1024) {
        unsigned long long key = sk[j];
        int idx = (int)(key & 0xFFFFFFFFull);
        float sc = g_score[idx];
        float4 bx = make_float4(0.f, 0.f, 0.f, 0.f);
        if (sc > -INFINITY) bx = g_roi4[idx];
        g_cand[j] = bx;
        g_tscore[j] = sc;
        out[OFF_OLD + j * 4 + 0] = bx.x;
        out[OFF_OLD + j * 4 + 1] = bx.y;
        out[OFF_OLD + j * 4 + 2] = bx.z;
        out[OFF_OLD + j * 4 + 3] = bx.w;
    }
}

// ---------------------------------------------------------------------------
// Kernel 5a: NMS suppression bitmask (unchanged).
// ---------------------------------------------------------------------------
#define MASK_ROWS_PER_BLK 50
#define MASK_SM_BYTES (N_PRE * 16 + N_PRE * 4)   // boxes + areas = 120000

__global__ __launch_bounds__(256)
void nms_mask_kernel()
{
    extern __shared__ unsigned char msm[];
    float4* s_box  = (float4*)msm;
    float*  s_area = (float*)(msm + N_PRE * 16);

    const int tid = threadIdx.x;
    for (int j = tid; j < N_PRE; j += 256) {
        float4 b = g_cand[j];
        s_box[j] = b;
        s_area[j] = __fmul_rn(__fsub_rn(b.z, b.x), __fsub_rn(b.w, b.y));
    }
    __syncthreads();

    const int iBase = blockIdx.x * MASK_ROWS_PER_BLK;
    for (int item = tid; item < MASK_ROWS_PER_BLK * NW; item += 256) {
        int r = item / NW;
        int w = item - r * NW;
        int i = iBase + r;
        float4 bi = s_box[i];
        float ai = s_area[i];
        unsigned int bits = 0;
        int j0 = w * 32;
#pragma unroll 8
        for (int bidx = 0; bidx < 32; ++bidx) {
            int j = j0 + bidx;
            if (j < N_PRE) {
                float4 bj = s_box[j];
                float yy0 = fmaxf(bj.x, bi.x);
                float xx0 = fmaxf(bj.y, bi.y);
                float yy1 = fminf(bj.z, bi.z);
                float xx1 = fminf(bj.w, bi.w);
                float inter = __fmul_rn(fmaxf(__fsub_rn(yy1, yy0), 0.0f),
                                        fmaxf(__fsub_rn(xx1, xx0), 0.0f));
                float iou = __fdiv_rn(inter,
                    __fadd_rn(__fsub_rn(__fadd_rn(s_area[j], ai), inter), 1e-9f));
                if (iou > NMS_THR) bits |= (1u << bidx);
            }
        }
        g_mask[(size_t)i * NW + w] = bits;
    }
}

// ---------------------------------------------------------------------------
// Kernel 5b: serial greedy pick over the bitmask (unchanged).
// ---------------------------------------------------------------------------
__global__ __launch_bounds__(256)
void nms_pick_kernel(float* __restrict__ out)
{
    __shared__ unsigned int s_removed[NW];
    __shared__ int s_V;
    __shared__ int s_next;

    const int tid = threadIdx.x;
    if (tid == 0) s_V = N_PRE;
    __syncthreads();

    for (int j = tid; j < N_PRE; j += 256)
        if (g_tscore[j] == -INFINITY) atomicMin(&s_V, j);
    __syncthreads();
    const int V = s_V;

    for (int w = tid; w < NW; w += 256) {
        int base = w * 32;
        unsigned int init;
        if (base >= V)            init = 0xFFFFFFFFu;
        else if (base + 32 <= V)  init = 0u;
        else                      init = 0xFFFFFFFFu << (V - base);
        s_removed[w] = init;
    }
    for (int k = tid; k < N_POST; k += 256) {
        out[OFF_ROIS + k * 4 + 0] = 0.0f;
        out[OFF_ROIS + k * 4 + 1] = 0.0f;
        out[OFF_ROIS + k * 4 + 2] = 0.0f;
        out[OFF_ROIS + k * 4 + 3] = 0.0f;
        out[OFF_RIDX + k] = 0.0f;
        out[OFF_RSC + k] = 0.0f;
    }
    __syncthreads();

    int curw = 0;
    for (int k = 0; k < N_POST; ++k) {
        if (tid == 0) {
            int pick = -1;
            while (curw < NW) {
                unsigned int lw = ~s_removed[curw];
                if (lw) { pick = curw * 32 + (__ffs(lw) - 1); break; }
                ++curw;
            }
            s_next = pick;
        }
        __syncthreads();
        int i = s_next;
        if (i < 0) break;

        if (tid == 0) {
            float4 b = g_cand[i];
            out[OFF_ROIS + k * 4 + 0] = b.x;
            out[OFF_ROIS + k * 4 + 1] = b.y;
            out[OFF_ROIS + k * 4 + 2] = b.z;
            out[OFF_ROIS + k * 4 + 3] = b.w;
            out[OFF_RSC + k] = g_tscore[i];
        }
        const unsigned int* row = &g_mask[(size_t)i * NW];
        for (int w = tid; w < NW; w += 256)
            s_removed[w] |= row[w];
        __syncthreads();
    }
}

// ---------------------------------------------------------------------------
// Launch
// ---------------------------------------------------------------------------
extern "C" void kernel_launch(void* const* d_in, const int* in_sizes, int n_in,
                              void* d_out, int out_size)
{
    const float* x      = (const float*)d_in[0];
    const int*   mask   = (const int*)d_in[1];
    const float* conv_w = (const float*)d_in[2];
    const float* conv_b = (const float*)d_in[3];
    const float* loc_w  = (const float*)d_in[4];
    const float* loc_b  = (const float*)d_in[5];
    const float* cls_w  = (const float*)d_in[6];
    const float* cls_b  = (const float*)d_in[7];
    const float* cos_w  = (const float*)d_in[8];
    const float* cos_b  = (const float*)d_in[9];
    const int*   img_h  = (const int*)d_in[10];
    const int*   img_w  = (const int*)d_in[11];
    float* out = (float*)d_out;

    cudaFuncSetAttribute(sort_kernel,
        cudaFuncAttributeMaxDynamicSharedMemorySize, NP * 8);
    cudaFuncSetAttribute(nms_mask_kernel,
        cudaFuncAttributeMaxDynamicSharedMemorySize, MASK_SM_BYTES);

    {
        dim3 gx(Cin, 16);
        pad_x_kernel<<<gx, 256>>>(x);
        pad_w_kernel<<<(unsigned)((TOTW + 255) / 256), 256>>>(conv_w);
    }
    conv3x3_kernel<<<1024, 256>>>(conv_b, mask);
    heads_kernel<<<NP / 256, 256>>>(loc_w, loc_b, cls_w, cls_b, cos_w, cos_b, out);
    roi_kernel<<<NP / 256, 256>>>(out, img_h, img_w);
    sort_kernel<<<1, 1024, NP * 8>>>(out);
    nms_mask_kernel<<<N_PRE / MASK_ROWS_PER_BLK, 256, MASK_SM_BYTES>>>();
    nms_pick_kernel<<<1, 256>>>(out);
}

// round 17
// speedup vs baseline: 1.0727x; 1.0602x over previous
#include <cuda_runtime.h>
#include <cuda_bf16.h>
#include <math.h>
#include <stdint.h>

// ---------------------------------------------------------------------------
// Problem constants
// ---------------------------------------------------------------------------
#define Hf 128
#define Wf 128
#define NP (Hf*Wf)          // 16384 spatial positions
#define Cin 512
#define Mch 512
#define N_PRE 6000
#define N_POST 300
#define NMS_THR 0.7f
#define MIN_SZ 16.0f
#define NW 188              // words per bitmask row (6000/32 -> 188)

// Output offsets (concatenated tuple, float32)
#define OFF_LOCS 0
#define OFF_ROIS 65536
#define OFF_RIDX 66736
#define OFF_ANCH 67036
#define OFF_CLS  132572
#define OFF_COS  247260
#define OFF_RSC  263644
#define OFF_OLD  263944

__device__ __constant__ float c_base_scales[7] =
    {16.0f, 9.0f, 14.0f, 21.0f, 33.0f, 54.0f, 93.0f};

// ---------------------------------------------------------------------------
// Device scratch (no allocations allowed)
// ---------------------------------------------------------------------------
#define XT_ROWS 34
#define XT_COLS 36
#define XT_SLAB (XT_ROWS * XT_COLS)          // 1224 floats per (tile, ch)
__device__ float g_xpad[(size_t)16 * Cin * XT_SLAB];   // ~40 MB
__device__ float g_wt[(size_t)64 * 64 * 8 * 9 * 8];    // ~9.4 MB
__device__ float g_h[(size_t)Mch * NP];     // conv output, 32 MB
__device__ float g_fg[NP];
__device__ float g_acos[NP];
__device__ float g_scale[NP];
__device__ int   g_assign[NP];
__device__ float4 g_roi4[NP];
__device__ float g_score[NP];
__device__ unsigned long long g_keys[NP];
__device__ float4 g_cand[N_PRE];
__device__ float  g_tscore[N_PRE];
__device__ unsigned int g_mask[(size_t)N_PRE * NW];    // 4.5 MB

// ---------------------------------------------------------------------------
// Packed f32x2 helpers (sm_103a): per-lane IEEE rn, bit-identical to scalar.
// ---------------------------------------------------------------------------
__device__ __forceinline__ unsigned long long f2_bcast(float x) {
    unsigned long long r;
    asm("mov.b64 %0, {%1, %1};" : "=l"(r) : "r"(__float_as_uint(x)));
    return r;
}
__device__ __forceinline__ unsigned long long f2_fma(unsigned long long a,
                                                     unsigned long long b,
                                                     unsigned long long c) {
    unsigned long long d;
    asm("fma.rn.f32x2 %0, %1, %2, %3;" : "=l"(d) : "l"(a), "l"(b), "l"(c));
    return d;
}
__device__ __forceinline__ unsigned long long f2_add(unsigned long long a,
                                                     unsigned long long b) {
    unsigned long long d;
    asm("add.rn.f32x2 %0, %1, %2;" : "=l"(d) : "l"(a), "l"(b));
    return d;
}
__device__ __forceinline__ unsigned long long f2_sub(unsigned long long a,
                                                     unsigned long long b) {
    unsigned long long d;
    asm("sub.rn.f32x2 %0, %1, %2;" : "=l"(d) : "l"(a), "l"(b));
    return d;
}
__device__ __forceinline__ void f2_unpack(float& lo, float& hi, unsigned long long v) {
    unsigned int a, b;
    asm("mov.b64 {%0, %1}, %2;" : "=r"(a), "=r"(b) : "l"(v));
    lo = __uint_as_float(a);
    hi = __uint_as_float(b);
}
__device__ __forceinline__ void kahan_add2(unsigned long long& sum,
                                           unsigned long long& comp,
                                           unsigned long long v) {
    unsigned long long y = f2_sub(v, comp);
    unsigned long long t = f2_add(sum, y);
    comp = f2_sub(f2_sub(t, sum), y);
    sum = t;
}
__device__ __forceinline__ void kahan_add(float& sum, float& comp, float v)
{
    float y = __fsub_rn(v, comp);
    float t = __fadd_rn(sum, y);
    comp = __fsub_rn(__fsub_rn(t, sum), y);
    sum = t;
}

// ---------------------------------------------------------------------------
// Kernel 0a: stage x into per-tile padded layout. Grid (c=512, tile=16).
// ---------------------------------------------------------------------------
__global__ __launch_bounds__(256)
void pad_x_kernel(const float* __restrict__ x)
{
    const int c    = blockIdx.x;
    const int tile = blockIdx.y;
    const int ty0 = (tile >> 2) * 32;
    const int tx0 = (tile & 3) * 32;
    float* dst = g_xpad + ((size_t)tile * Cin + c) * XT_SLAB;
    const float* src = x + (size_t)c * NP;
#pragma unroll
    for (int k = 0; k < 5; ++k) {
        int e = threadIdx.x + k * 256;
        if (e < XT_SLAB) {
            int ly = e / XT_COLS;
            int lx = e - ly * XT_COLS;
            int gy = ty0 - 1 + ly;
            int gx = tx0 - 1 + lx;
            float v = 0.0f;
            if (lx < 34 && gy >= 0 && gy < Hf && gx >= 0 && gx < Wf)
                v = src[gy * Wf + gx];
            dst[e] = v;
        }
    }
}

// ---------------------------------------------------------------------------
// Kernel 0b: transpose weights into [mb][ccb][c][tap][m].
// ---------------------------------------------------------------------------
#define TOTW ((size_t)64 * 64 * 576)

__global__ __launch_bounds__(256)
void pad_w_kernel(const float* __restrict__ w)
{
    unsigned int d = blockIdx.x * 256 + threadIdx.x;
    if (d >= (unsigned int)TOTW) return;
    int m   = (int)(d & 7);
    int t   = (int)((d >> 3) % 9);
    int c   = (int)((d / 72) & 7);
    int ccb = (int)((d / 576) & 63);
    int mb  = (int)(d / 36864);
    g_wt[d] = w[(size_t)(mb * 8 + m) * (Cin * 9) + (ccb * 8 + c) * 9 + t];
}

// ---------------------------------------------------------------------------
// Kernel 1: conv — R11-passing version verbatim (bit-identical math).
// ---------------------------------------------------------------------------
#define XS_C 8
#define XS_H 34
#define XS_W 36

__global__ __launch_bounds__(256, 2)
void conv3x3_kernel(const float* __restrict__ b,
                    const int*   __restrict__ mask)
{
    __shared__ float xs[XS_C * XS_H * XS_W];        // 9792 floats
    __shared__ float ws[XS_C * 9 * 8];              // 576 floats

    const int tid  = threadIdx.x;
    const int tile = blockIdx.x & 15;
    const int mb   = blockIdx.x >> 4;               // 0..63
    const int mBase = mb * 8;
    const int ty0 = ((tile >> 2) * 32);
    const int tx0 = ((tile & 3) * 32);

    const int ty = tid >> 4, tx = tid & 15;
    const int py = ty * 2, px = tx * 2;

    unsigned long long sum2[4][4], comp2[4][4];
#pragma unroll
    for (int q = 0; q < 4; ++q)
#pragma unroll
        for (int mp = 0; mp < 4; ++mp) { sum2[q][mp] = 0ull; comp2[q][mp] = 0ull; }

    const float4* xsrc0 = (const float4*)(g_xpad + (size_t)tile * Cin * XT_SLAB);
    const float4* wsrc0 = (const float4*)(g_wt + (size_t)mb * 64 * 576);

    for (int ccb = 0; ccb < 64; ++ccb) {
        __syncthreads();
        {
            const float4* src = xsrc0 + (size_t)ccb * (8 * XT_SLAB / 4);
            float4* dst = (float4*)xs;
#pragma unroll
            for (int k = 0; k < 10; ++k) {          // ceil(2448/256) = 10
                int i = tid + k * 256;
                if (i < 2448) dst[i] = src[i];
            }
        }
        {
            const float4* src = wsrc0 + (size_t)ccb * 144;
            if (tid < 144) ((float4*)ws)[tid] = src[tid];
        }
        __syncthreads();

        unsigned long long part2[4][4];
#pragma unroll
        for (int q = 0; q < 4; ++q)
#pragma unroll
            for (int mp = 0; mp < 4; ++mp) part2[q][mp] = 0ull;

#pragma unroll 1
        for (int c = 0; c < XS_C; ++c) {
            const float* xc = xs + c * (XS_H * XS_W);
            const float* wc = ws + c * 72;
#pragma unroll
            for (int ky = 0; ky < 3; ++ky) {
#pragma unroll
                for (int kx = 0; kx < 3; ++kx) {
                    const unsigned long long* wp =
                        (const unsigned long long*)(wc + (ky * 3 + kx) * 8);
                    unsigned long long wv[4];
                    wv[0] = wp[0]; wv[1] = wp[1]; wv[2] = wp[2]; wv[3] = wp[3];
                    unsigned long long xp[4];
                    xp[0] = f2_bcast(xc[(py + ky) * XS_W + (px + kx)]);
                    xp[1] = f2_bcast(xc[(py + ky) * XS_W + (px + kx + 1)]);
                    xp[2] = f2_bcast(xc[(py + ky + 1) * XS_W + (px + kx)]);
                    xp[3] = f2_bcast(xc[(py + ky + 1) * XS_W + (px + kx + 1)]);
#pragma unroll
                    for (int mp = 0; mp < 4; ++mp) {
                        part2[0][mp] = f2_fma(xp[0], wv[mp], part2[0][mp]);
                        part2[1][mp] = f2_fma(xp[1], wv[mp], part2[1][mp]);
                        part2[2][mp] = f2_fma(xp[2], wv[mp], part2[2][mp]);
                        part2[3][mp] = f2_fma(xp[3], wv[mp], part2[3][mp]);
                    }
                }
            }
        }
#pragma unroll
        for (int q = 0; q < 4; ++q)
#pragma unroll
            for (int mp = 0; mp < 4; ++mp)
                kahan_add2(sum2[q][mp], comp2[q][mp], part2[q][mp]);
    }

    float mv[4];
#pragma unroll
    for (int q = 0; q < 4; ++q) {
        int gy = ty0 + py + (q >> 1);
        int gx = tx0 + px + (q & 1);
        mv[q] = (float)mask[gy * Wf + gx];
    }
#pragma unroll
    for (int mp = 0; mp < 4; ++mp) {
        float bias0 = b[mBase + 2 * mp];
        float bias1 = b[mBase + 2 * mp + 1];
#pragma unroll
        for (int q = 0; q < 4; ++q) {
            int gy = ty0 + py + (q >> 1);
            int gx = tx0 + px + (q & 1);
            float s0, s1, c0, c1;
            f2_unpack(s0, s1, sum2[q][mp]);
            f2_unpack(c0, c1, comp2[q][mp]);
            float v0 = __fadd_rn(__fadd_rn(s0, c0), bias0);
            float v1 = __fadd_rn(__fadd_rn(s1, c1), bias1);
            v0 = fmaxf(v0, 0.0f) * mv[q];
            v1 = fmaxf(v1, 0.0f) * mv[q];
            g_h[(size_t)(mBase + 2 * mp) * NP + gy * Wf + gx] = v0;
            g_h[(size_t)(mBase + 2 * mp + 1) * NP + gy * Wf + gx] = v1;
        }
    }
}

// ---------------------------------------------------------------------------
// Kernel 2: heads — R11-passing version verbatim (64 x 256, best measured).
// ---------------------------------------------------------------------------
__global__ __launch_bounds__(256)
void heads_kernel(const float* __restrict__ loc_w, const float* __restrict__ loc_b,
                  const float* __restrict__ cls_w, const float* __restrict__ cls_b,
                  const float* __restrict__ cos_w, const float* __restrict__ cos_b,
                  float* __restrict__ out)
{
    __shared__ float sw[Cin * 12];
    const int tid = threadIdx.x;
    for (int i = tid; i < Cin * 12; i += 256) {
        int o = i / Cin;
        int c = i - o * Cin;
        float v;
        if (o < 4)       v = loc_w[o * Cin + c];
        else if (o < 11) v = cls_w[(o - 4) * Cin + c];
        else             v = cos_w[c];
        sw[c * 12 + o] = v;
    }
    __syncthreads();

    const int p = blockIdx.x * 256 + tid;
    float sum[12], comp[12];
#pragma unroll
    for (int o = 0; o < 12; ++o) { sum[o] = 0.0f; comp[o] = 0.0f; }

#pragma unroll 1
    for (int c = 0; c < Cin; c += 8) {
        float part[12];
#pragma unroll
        for (int o = 0; o < 12; ++o) part[o] = 0.0f;
#pragma unroll
        for (int k = 0; k < 8; ++k) {
            float hv = g_h[(size_t)(c + k) * NP + p];
            const float* wv = &sw[(c + k) * 12];
#pragma unroll
            for (int o = 0; o < 12; ++o)
                part[o] = fmaf(hv, wv[o], part[o]);
        }
#pragma unroll
        for (int o = 0; o < 12; ++o)
            kahan_add(sum[o], comp[o], part[o]);
    }
    float acc[12];
#pragma unroll
    for (int o = 0; o < 12; ++o) acc[o] = __fadd_rn(sum[o], comp[o]);

#pragma unroll
    for (int o = 0; o < 4; ++o)
        out[OFF_LOCS + p * 4 + o] = __fadd_rn(acc[o], loc_b[o]);

    float z[7];
#pragma unroll
    for (int o = 0; o < 7; ++o) {
        z[o] = __fadd_rn(acc[4 + o], cls_b[o]);
        out[OFF_CLS + p * 7 + o] = z[o];
    }
    float zmax = z[0];
    int am = 0;
#pragma unroll
    for (int o = 1; o < 7; ++o) {
        if (z[o] > zmax) zmax = z[o];
        if (z[o] > z[am]) am = o;
    }
    float ssum = 0.0f;
#pragma unroll
    for (int o = 0; o < 7; ++o) ssum = __fadd_rn(ssum, expf(__fsub_rn(z[o], zmax)));
    float p0 = __fdiv_rn(expf(__fsub_rn(z[0], zmax)), ssum);
    g_fg[p] = __fsub_rn(1.0f, p0);
    g_assign[p] = am;
    g_scale[p] = c_base_scales[am];

    float zc = __fadd_rn(acc[11], cos_b[0]);
    float s = __fdiv_rn(1.0f, __fadd_rn(1.0f, expf(-zc)));
    out[OFF_COS + p] = s;
    g_acos[p] = (s == 0.0f) ? 1e-5f : s;
}

// ---------------------------------------------------------------------------
// Kernel 3: anchors, loc2bbox, clip, validity, scores, sort keys (unchanged)
// ---------------------------------------------------------------------------
__global__ __launch_bounds__(256)
void roi_kernel(float* __restrict__ out,
                const int* __restrict__ img_h_p, const int* __restrict__ img_w_p)
{
    const int p = blockIdx.x * 256 + threadIdx.x;
    const float img_h = (float)img_h_p[0];
    const float img_w = (float)img_w_p[0];

    float a0c = g_acos[0];
    float s0  = g_scale[0];
    float anchor_h = s0 * sqrtf(1.0f / (a0c * a0c) - 1.0f);

    float ay = (float)(p >> 7) * 8.0f + 4.0f;
    float ax = (float)(p & 127) * 8.0f + 4.0f;
    float aw = g_scale[p];

    float a_0 = ay - 0.5f * anchor_h;
    float a_1 = ax - 0.5f * aw;
    float a_2 = ay + 0.5f * anchor_h;
    float a_3 = ax + 0.5f * aw;
    out[OFF_ANCH + p * 4 + 0] = a_0;
    out[OFF_ANCH + p * 4 + 1] = a_1;
    out[OFF_ANCH + p * 4 + 2] = a_2;
    out[OFF_ANCH + p * 4 + 3] = a_3;

    float h  = __fsub_rn(a_2, a_0);
    float w  = __fsub_rn(a_3, a_1);
    float cy = __fadd_rn(a_0, __fmul_rn(0.5f, h));
    float cx = __fadd_rn(a_1, __fmul_rn(0.5f, w));
    float l0 = out[OFF_LOCS + p * 4 + 0];
    float l1 = out[OFF_LOCS + p * 4 + 1];
    float l2 = out[OFF_LOCS + p * 4 + 2];
    float l3 = out[OFF_LOCS + p * 4 + 3];
    float ncy = __fadd_rn(__fmul_rn(l0, h), cy);
    float ncx = __fadd_rn(__fmul_rn(l1, w), cx);
    float nh  = __fmul_rn(expf(l2), h);
    float nw  = __fmul_rn(expf(l3), w);
    float r0 = fminf(fmaxf(__fsub_rn(ncy, __fmul_rn(0.5f, nh)), 0.0f), img_h);
    float r1 = fminf(fmaxf(__fsub_rn(ncx, __fmul_rn(0.5f, nw)), 0.0f), img_w);
    float r2 = fminf(fmaxf(__fadd_rn(ncy, __fmul_rn(0.5f, nh)), 0.0f), img_h);
    float r3 = fminf(fmaxf(__fadd_rn(ncx, __fmul_rn(0.5f, nw)), 0.0f), img_w);
    g_roi4[p] = make_float4(r0, r1, r2, r3);

    float hs = __fsub_rn(r2, r0), ws = __fsub_rn(r3, r1);
    bool valid = (g_assign[p] > 0) && (hs >= MIN_SZ) && (ws >= MIN_SZ);
    float score = valid ? g_fg[p] : -INFINITY;
    g_score[p] = score;

    unsigned int u = __float_as_uint(score);
    unsigned int m = (u & 0x80000000u) ? ~u : (u | 0x80000000u);
    g_keys[p] = ((unsigned long long)(m ^ 0xFFFFFFFFu) << 32) |
                (unsigned long long)(unsigned int)p;
}

// ---------------------------------------------------------------------------
// Multi-block bitonic sort: exact same 105-phase network as the monolithic
// kernel, partitioned so phases with j<=1024 run in-segment (8 blocks of
// 2048 in smem) and the 6 cross-segment phases (j>=2048) run as tiny gmem
// passes with launch-boundary grid sync. Directions use GLOBAL indices.
// ---------------------------------------------------------------------------
#define SEG 2048

// full local network k=2..2048
__global__ __launch_bounds__(1024)
void sortA_kernel()
{
    __shared__ unsigned long long sk[SEG];
    const int tid = threadIdx.x;
    const int base = blockIdx.x * SEG;
    sk[tid] = g_keys[base + tid];
    sk[tid + 1024] = g_keys[base + tid + 1024];
    __syncthreads();
    for (int k = 2; k <= SEG; k <<= 1) {
        for (int j = k >> 1; j > 0; j >>= 1) {
            for (int i = tid; i < SEG; i += 1024) {
                int ixj = i ^ j;
                if (ixj > i) {
                    bool up = (((base + i) & k) == 0);
                    unsigned long long a = sk[i], b2 = sk[ixj];
                    if ((a > b2) == up) { sk[i] = b2; sk[ixj] = a; }
                }
            }
            __syncthreads();
        }
    }
    g_keys[base + tid] = sk[tid];
    g_keys[base + tid + 1024] = sk[tid + 1024];
}

// one cross-segment phase (k, j) with j >= SEG; 8192 pairs
__global__ __launch_bounds__(256)
void gpass_kernel(int k, int j)
{
    int p = blockIdx.x * 256 + threadIdx.x;
    if (p >= NP / 2) return;
    int i = ((p & ~(j - 1)) << 1) | (p & (j - 1));
    int ixj = i | j;
    bool up = ((i & k) == 0);
    unsigned long long a = g_keys[i], b2 = g_keys[ixj];
    if ((a > b2) == up) { g_keys[i] = b2; g_keys[ixj] = a; }
}

// local phases j=1024..1 for a given k; optional top-N_PRE writeout
__global__ __launch_bounds__(1024)
void lpass_kernel(int k, int writeout, float* __restrict__ out)
{
    __shared__ unsigned long long sk[SEG];
    const int tid = threadIdx.x;
    const int base = blockIdx.x * SEG;
    sk[tid] = g_keys[base + tid];
    sk[tid + 1024] = g_keys[base + tid + 1024];
    __syncthreads();
    for (int j = 1024; j > 0; j >>= 1) {
        for (int i = tid; i < SEG; i += 1024) {
            int ixj = i ^ j;
            if (ixj > i) {
                bool up = (((base + i) & k) == 0);
                unsigned long long a = sk[i], b2 = sk[ixj];
                if ((a > b2) == up) { sk[i] = b2; sk[ixj] = a; }
            }
        }
        __syncthreads();
    }
    g_keys[base + tid] = sk[tid];
    g_keys[base + tid + 1024] = sk[tid + 1024];
    if (writeout) {
        for (int l = tid; l < SEG; l += 1024) {
            int gi = base + l;
            if (gi < N_PRE) {
                unsigned long long key = sk[l];
                int idx = (int)(key & 0xFFFFFFFFull);
                float sc = g_score[idx];
                float4 bx = make_float4(0.f, 0.f, 0.f, 0.f);
                if (sc > -INFINITY) bx = g_roi4[idx];
                g_cand[gi] = bx;
                g_tscore[gi] = sc;
                out[OFF_OLD + gi * 4 + 0] = bx.x;
                out[OFF_OLD + gi * 4 + 1] = bx.y;
                out[OFF_OLD + gi * 4 + 2] = bx.z;
                out[OFF_OLD + gi * 4 + 3] = bx.w;
            }
        }
    }
}

// ---------------------------------------------------------------------------
// Kernel 5a: NMS suppression bitmask (unchanged).
// ---------------------------------------------------------------------------
#define MASK_ROWS_PER_BLK 50
#define MASK_SM_BYTES (N_PRE * 16 + N_PRE * 4)   // boxes + areas = 120000

__global__ __launch_bounds__(256)
void nms_mask_kernel()
{
    extern __shared__ unsigned char msm[];
    float4* s_box  = (float4*)msm;
    float*  s_area = (float*)(msm + N_PRE * 16);

    const int tid = threadIdx.x;
    for (int j = tid; j < N_PRE; j += 256) {
        float4 b = g_cand[j];
        s_box[j] = b;
        s_area[j] = __fmul_rn(__fsub_rn(b.z, b.x), __fsub_rn(b.w, b.y));
    }
    __syncthreads();

    const int iBase = blockIdx.x * MASK_ROWS_PER_BLK;
    for (int item = tid; item < MASK_ROWS_PER_BLK * NW; item += 256) {
        int r = item / NW;
        int w = item - r * NW;
        int i = iBase + r;
        float4 bi = s_box[i];
        float ai = s_area[i];
        unsigned int bits = 0;
        int j0 = w * 32;
#pragma unroll 8
        for (int bidx = 0; bidx < 32; ++bidx) {
            int j = j0 + bidx;
            if (j < N_PRE) {
                float4 bj = s_box[j];
                float yy0 = fmaxf(bj.x, bi.x);
                float xx0 = fmaxf(bj.y, bi.y);
                float yy1 = fminf(bj.z, bi.z);
                float xx1 = fminf(bj.w, bi.w);
                float inter = __fmul_rn(fmaxf(__fsub_rn(yy1, yy0), 0.0f),
                                        fmaxf(__fsub_rn(xx1, xx0), 0.0f));
                float iou = __fdiv_rn(inter,
                    __fadd_rn(__fsub_rn(__fadd_rn(s_area[j], ai), inter), 1e-9f));
                if (iou > NMS_THR) bits |= (1u << bidx);
            }
        }
        g_mask[(size_t)i * NW + w] = bits;
    }
}

// ---------------------------------------------------------------------------
// Kernel 5b: serial greedy pick over the bitmask (unchanged).
// ---------------------------------------------------------------------------
__global__ __launch_bounds__(256)
void nms_pick_kernel(float* __restrict__ out)
{
    __shared__ unsigned int s_removed[NW];
    __shared__ int s_V;
    __shared__ int s_next;

    const int tid = threadIdx.x;
    if (tid == 0) s_V = N_PRE;
    __syncthreads();

    for (int j = tid; j < N_PRE; j += 256)
        if (g_tscore[j] == -INFINITY) atomicMin(&s_V, j);
    __syncthreads();
    const int V = s_V;

    for (int w = tid; w < NW; w += 256) {
        int base = w * 32;
        unsigned int init;
        if (base >= V)            init = 0xFFFFFFFFu;
        else if (base + 32 <= V)  init = 0u;
        else                      init = 0xFFFFFFFFu << (V - base);
        s_removed[w] = init;
    }
    for (int k = tid; k < N_POST; k += 256) {
        out[OFF_ROIS + k * 4 + 0] = 0.0f;
        out[OFF_ROIS + k * 4 + 1] = 0.0f;
        out[OFF_ROIS + k * 4 + 2] = 0.0f;
        out[OFF_ROIS + k * 4 + 3] = 0.0f;
        out[OFF_RIDX + k] = 0.0f;
        out[OFF_RSC + k] = 0.0f;
    }
    __syncthreads();

    int curw = 0;
    for (int k = 0; k < N_POST; ++k) {
        if (tid == 0) {
            int pick = -1;
            while (curw < NW) {
                unsigned int lw = ~s_removed[curw];
                if (lw) { pick = curw * 32 + (__ffs(lw) - 1); break; }
                ++curw;
            }
            s_next = pick;
        }
        __syncthreads();
        int i = s_next;
        if (i < 0) break;

        if (tid == 0) {
            float4 b = g_cand[i];
            out[OFF_ROIS + k * 4 + 0] = b.x;
            out[OFF_ROIS + k * 4 + 1] = b.y;
            out[OFF_ROIS + k * 4 + 2] = b.z;
            out[OFF_ROIS + k * 4 + 3] = b.w;
            out[OFF_RSC + k] = g_tscore[i];
        }
        const unsigned int* row = &g_mask[(size_t)i * NW];
        for (int w = tid; w < NW; w += 256)
            s_removed[w] |= row[w];
        __syncthreads();
    }
}

// ---------------------------------------------------------------------------
// Launch
// ---------------------------------------------------------------------------
extern "C" void kernel_launch(void* const* d_in, const int* in_sizes, int n_in,
                              void* d_out, int out_size)
{
    const float* x      = (const float*)d_in[0];
    const int*   mask   = (const int*)d_in[1];
    const float* conv_w = (const float*)d_in[2];
    const float* conv_b = (const float*)d_in[3];
    const float* loc_w  = (const float*)d_in[4];
    const float* loc_b  = (const float*)d_in[5];
    const float* cls_w  = (const float*)d_in[6];
    const float* cls_b  = (const float*)d_in[7];
    const float* cos_w  = (const float*)d_in[8];
    const float* cos_b  = (const float*)d_in[9];
    const int*   img_h  = (const int*)d_in[10];
    const int*   img_w  = (const int*)d_in[11];
    float* out = (float*)d_out;

    cudaFuncSetAttribute(nms_mask_kernel,
        cudaFuncAttributeMaxDynamicSharedMemorySize, MASK_SM_BYTES);

    {
        dim3 gx(Cin, 16);
        pad_x_kernel<<<gx, 256>>>(x);
        pad_w_kernel<<<(unsigned)((TOTW + 255) / 256), 256>>>(conv_w);
    }
    conv3x3_kernel<<<1024, 256>>>(conv_b, mask);
    heads_kernel<<<NP / 256, 256>>>(loc_w, loc_b, cls_w, cls_b, cos_w, cos_b, out);
    roi_kernel<<<NP / 256, 256>>>(out, img_h, img_w);

    // bitonic sort, multi-block partition (identical network)
    sortA_kernel<<<8, 1024>>>();
    gpass_kernel<<<32, 256>>>(4096, 2048);
    lpass_kernel<<<8, 1024>>>(4096, 0, out);
    gpass_kernel<<<32, 256>>>(8192, 4096);
    gpass_kernel<<<32, 256>>>(8192, 2048);
    lpass_kernel<<<8, 1024>>>(8192, 0, out);
    gpass_kernel<<<32, 256>>>(16384, 8192);
    gpass_kernel<<<32, 256>>>(16384, 4096);
    gpass_kernel<<<32, 256>>>(16384, 2048);
    lpass_kernel<<<8, 1024>>>(16384, 1, out);

    nms_mask_kernel<<<N_PRE / MASK_ROWS_PER_BLK, 256, MASK_SM_BYTES>>>();
    nms_pick_kernel<<<1, 256>>>(out);
}